// round 9
// baseline (speedup 1.0000x reference)
#include <cuda_runtime.h>
#include <stdint.h>

#define N        100800
#define NC       80
#define STRIDE   85
#define MAX_NMS  4096
#define MAX_DET  1000
#define CAP      16384
#define NB       256            // key>>16 - KBASE in [0, 180)
#define KBASE    0x3ECCu
#define CONF_T   0.4f
#define IOU_T    0.45f
#define MAX_WH   7680.0f
#define ECAP     8192
#define NBLK     148
#define NTHR     1024
#define NTILE    2080           // 64*65/2 upper-tri 64x64 tiles

typedef unsigned long long u64;

// ---------------- scratch (static __device__, allocation-free) ----------------
__device__ unsigned int g_hist[NB];
__device__ unsigned int g_boff[NB];
__device__ unsigned int g_bcnt[NB];
__device__ unsigned int g_key[N];
__device__ unsigned int g_cutoff, g_total, g_bmax, g_ecnt;
__device__ u64          g_cand[CAP];
__device__ float4       g_obox[MAX_NMS];
__device__ float        g_area[MAX_NMS];
__device__ float4       g_bbox[MAX_NMS];
__device__ float        g_score[MAX_NMS];
__device__ float        g_clsf[MAX_NMS];
__device__ unsigned int g_edge[ECAP];

// ---------------- software grid barrier (all 148 CTAs co-resident) ----------
__device__ unsigned int          bar_cnt = 0;
__device__ volatile unsigned int bar_gen = 0;

__device__ __forceinline__ void gsync() {
    __syncthreads();
    if (threadIdx.x == 0) {
        unsigned int gen = bar_gen;
        __threadfence();                       // release prior writes
        if (atomicAdd(&bar_cnt, 1u) == NBLK - 1u) {
            atomicExch(&bar_cnt, 0u);
            __threadfence();
            bar_gen = gen + 1u;                // publish
        } else {
            while (bar_gen == gen) {}
            __threadfence();                   // acquire
        }
    }
    __syncthreads();
}

// ---------------- decode one rank from sorted candidate key ----------------
__device__ __forceinline__ void decode_rank(const float* __restrict__ pred,
                                            u64 key, int r) {
    unsigned int kb  = (unsigned int)(key >> 32);
    unsigned int idx = ~(unsigned int)(key & 0xFFFFFFFFu);
    const float* row = pred + (size_t)idx * STRIDE;
    float x = row[0], y = row[1], w = row[2], h = row[3], obj = row[4];
    float bestv = -1.0f; int bestc = 0;
#pragma unroll 8
    for (int c = 0; c < NC; c++) {
        float p = __fmul_rn(row[5 + c], obj);
        if (p > bestv) { bestv = p; bestc = c; }
    }
    float hw = __fmul_rn(w, 0.5f), hh = __fmul_rn(h, 0.5f);
    float x1 = __fsub_rn(x, hw), y1 = __fsub_rn(y, hh);
    float x2 = __fadd_rn(x, hw), y2 = __fadd_rn(y, hh);
    float cf = (float)bestc;
    float off = __fmul_rn(cf, MAX_WH);
    float ox1 = __fadd_rn(x1, off), oy1 = __fadd_rn(y1, off);
    float ox2 = __fadd_rn(x2, off), oy2 = __fadd_rn(y2, off);
    float area = __fmul_rn(__fsub_rn(ox2, ox1), __fsub_rn(oy2, oy1));
    g_obox[r]  = make_float4(ox1, oy1, ox2, oy2);
    g_area[r]  = area;
    g_bbox[r]  = make_float4(x1, y1, x2, y2);
    g_score[r] = __uint_as_float(kb);
    g_clsf[r]  = cf;
}

// ---------------- the whole pipeline in one persistent kernel ----------------
__global__ void __launch_bounds__(NTHR, 1)
yolo_all(const float* __restrict__ pred, float* __restrict__ out) {
    __shared__ u64          sbuf[4096];     // 32KB: bucket sort (u64) / edges (u32)
    __shared__ unsigned int shist[NB];
    __shared__ float4       cob[64];
    __shared__ float        car[64];
    __shared__ u64          keep[64];
    __shared__ unsigned int pref[64];
    __shared__ int          s_bmax;

    const int tid = threadIdx.x;
    const int bid = blockIdx.x;

    // ---------- P1: zero counters + output ----------
    if (bid == 0) {
        if (tid < NB) g_hist[tid] = 0u;
        if (tid == 0) g_ecnt = 0u;
    }
    if (bid == 1) {
        for (int j = tid; j < MAX_DET * 6; j += NTHR) out[j] = 0.0f;
    }
    gsync();

    // ---------- P2: warp-per-anchor score + smem histogram ----------
    if (tid < NB) shist[tid] = 0u;
    __syncthreads();
    {
        int lane = tid & 31;
        int gw   = bid * (NTHR / 32) + (tid >> 5);
        const int nwarps = NBLK * (NTHR / 32);
        for (int a = gw; a < N; a += nwarps) {
            const float* r = pred + (size_t)a * STRIDE;
            float v0 = r[lane];
            float v1 = r[lane + 32];
            float v2 = (lane < 21) ? r[lane + 64] : 0.0f;
            float obj = __shfl_sync(0xffffffffu, v0, 4);
            float m = -1.0f;
            if (lane >= 5) m = __fmul_rn(v0, obj);
            m = fmaxf(m, __fmul_rn(v1, obj));
            if (lane < 21) m = fmaxf(m, __fmul_rn(v2, obj));
#pragma unroll
            for (int off = 16; off > 0; off >>= 1)
                m = fmaxf(m, __shfl_xor_sync(0xffffffffu, m, off));
            if (lane == 0) {
                unsigned int key = 0u;
                if (m > CONF_T) key = __float_as_uint(m);
                g_key[a] = key;
                if (key) {
                    unsigned int b = (key >> 16) - KBASE;
                    if (b > 255u) b = 255u;
                    atomicAdd(&shist[b], 1u);
                }
            }
        }
    }
    __syncthreads();
    if (tid < NB && shist[tid]) atomicAdd(&g_hist[tid], shist[tid]);
    gsync();

    // ---------- P3: suffix scan -> offsets, cutoff, total, bmax (block 0) ----
    if (bid == 0) {
        if (tid == 0) s_bmax = 0;
        unsigned int h = 0u;
        if (tid < NB) { h = g_hist[tid]; shist[tid] = h; }
        __syncthreads();
        for (int off = 1; off < NB; off <<= 1) {
            unsigned int v = 0u;
            if (tid < NB && tid + off < NB) v = shist[tid + off];
            __syncthreads();
            if (tid < NB) shist[tid] += v;
            __syncthreads();
        }
        if (tid < NB) {
            g_boff[tid] = (tid < NB - 1) ? shist[tid + 1] : 0u;
            g_bcnt[tid] = 0u;
            unsigned int st = shist[tid];
            if (st >= (unsigned)MAX_NMS &&
                (tid == NB - 1 || shist[tid + 1] < (unsigned)MAX_NMS)) {
                g_cutoff = (unsigned)tid;
                g_total  = st;
            }
            if (h) atomicMax(&s_bmax, tid);
        }
        __syncthreads();
        if (tid == 0) {
            g_bmax = (unsigned)s_bmax;
            if (shist[0] < (unsigned)MAX_NMS) { g_cutoff = 0u; g_total = shist[0]; }
        }
    }
    gsync();

    // ---------- P4: gather candidates into bucket segments ----------
    {
        unsigned int cutoff = g_cutoff;
        for (int i = bid * NTHR + tid; i < N; i += NBLK * NTHR) {
            unsigned int key = g_key[i];
            if (!key) continue;
            unsigned int b = (key >> 16) - KBASE;
            if (b > 255u) b = 255u;
            if (b < cutoff) continue;
            unsigned int pos = g_boff[b] + atomicAdd(&g_bcnt[b], 1u);
            if (pos < CAP)
                g_cand[pos] = ((u64)key << 32) | (unsigned int)(~(unsigned int)i);
        }
    }
    gsync();

    // ---------- P5: per-bucket bitonic sort (descending) + fused decode ------
    {
        unsigned int cutoff = g_cutoff, bmax = g_bmax;
        unsigned int limit = g_total;
        if (limit > (unsigned)MAX_NMS) limit = MAX_NMS;
        for (unsigned int b = cutoff + bid; b <= bmax; b += NBLK) {
            unsigned int L = g_hist[b];
            if (L == 0) continue;
            unsigned int off = g_boff[b];
            if (off >= limit) continue;
            if (L > 4096u) L = 4096u;
            if (L == 1) {
                if (tid == 0 && off < limit) decode_rank(pred, g_cand[off], off);
                continue;
            }
            unsigned int P = 2; while (P < L) P <<= 1;
            for (unsigned int j = tid; j < P; j += NTHR)
                sbuf[j] = (j < L) ? g_cand[off + j] : 0ULL;
            __syncthreads();
            for (unsigned int k = 2; k <= P; k <<= 1) {
                for (unsigned int j = k >> 1; j > 0; j >>= 1) {
                    for (unsigned int p = tid; p < P / 2; p += NTHR) {
                        unsigned int i = ((p & ~(j - 1)) << 1) | (p & (j - 1));
                        u64 a = sbuf[i], c = sbuf[i + j];
                        bool sw = ((i & k) == 0) ? (a < c) : (a > c); // descending
                        if (sw) { sbuf[i] = c; sbuf[i + j] = a; }
                    }
                    __syncthreads();
                }
            }
            for (unsigned int j = tid; j < L; j += NTHR) {
                unsigned int r = off + j;
                if (r < limit) decode_rank(pred, sbuf[j], (int)r);
            }
            __syncthreads();
        }
    }
    gsync();

    // ---------- P6: sparse suppression edge list (upper-tri tiles) ----------
    for (int e = bid; e < NTILE; e += NBLK) {
        int rb = 0, rem = e;
        while (rem >= 64 - rb) { rem -= 64 - rb; rb++; }
        int cb = rb + rem;
        if (tid < 64) {
            cob[tid] = g_obox[cb * 64 + tid];
            car[tid] = g_area[cb * 64 + tid];
        }
        __syncthreads();
        int r   = tid >> 4;
        int row = rb * 64 + r;
        float4 a = g_obox[row];
        float  aa = g_area[row];
#pragma unroll
        for (int q = 0; q < 4; q++) {
            int k   = (tid & 15) + q * 16;
            int col = cb * 64 + k;
            if (col > row) {
                float4 bbx = cob[k];
                float ltx = fmaxf(a.x, bbx.x), lty = fmaxf(a.y, bbx.y);
                float rbx = fminf(a.z, bbx.z), rby = fminf(a.w, bbx.w);
                float w = fmaxf(__fsub_rn(rbx, ltx), 0.0f);
                float h = fmaxf(__fsub_rn(rby, lty), 0.0f);
                float inter = __fmul_rn(w, h);
                if (inter > 0.0f) {
                    float denom = __fadd_rn(__fsub_rn(__fadd_rn(aa, car[k]), inter), 1e-9f);
                    float iou = __fdiv_rn(inter, denom);
                    if (iou > IOU_T) {
                        unsigned int p = atomicAdd(&g_ecnt, 1u);
                        if (p < ECAP)
                            g_edge[p] = ((unsigned int)row << 12) | (unsigned int)col;
                    }
                }
            }
        }
        __syncthreads();
    }
    gsync();

    // ---------- P7: block 0 only — sort edges, greedy, emit ----------
    if (bid != 0) return;
    {
        unsigned int* se = (unsigned int*)sbuf;     // reuse: 8192 u32
        unsigned int E = g_ecnt;
        if (E > ECAP) E = ECAP;
        unsigned int total = g_total;
        if (total > (unsigned)MAX_NMS) total = MAX_NMS;

        if (tid < 64) {
            unsigned int base = tid * 64u;
            u64 w;
            if (total >= base + 64u) w = ~0ULL;
            else if (total <= base)  w = 0ULL;
            else w = (1ULL << (total - base)) - 1ULL;
            keep[tid] = w;
        }

        unsigned int P = 1; while (P < E) P <<= 1;
        for (unsigned int i = tid; i < P; i += NTHR)
            se[i] = (i < E) ? g_edge[i] : 0xFFFFFFFFu;
        __syncthreads();

        if (E > 1) {
            for (unsigned int k = 2; k <= P; k <<= 1) {
                for (unsigned int j = k >> 1; j > 0; j >>= 1) {
                    for (unsigned int p = tid; p < P / 2; p += NTHR) {
                        unsigned int i = ((p & ~(j - 1)) << 1) | (p & (j - 1));
                        unsigned int a = se[i], c = se[i + j];
                        bool sw = ((i & k) == 0) ? (a > c) : (a < c); // ascending
                        if (sw) { se[i] = c; se[i + j] = a; }
                    }
                    __syncthreads();
                }
            }
        }

        // sequential greedy: edges ascending by src => exact fori_loop semantics
        if (tid == 0) {
            for (unsigned int e = 0; e < E; e++) {
                unsigned int kk = se[e];
                unsigned int s = kk >> 12, d = kk & 4095u;
                if ((keep[s >> 6] >> (s & 63u)) & 1ULL)
                    keep[d >> 6] &= ~(1ULL << (d & 63u));
            }
            unsigned int run = 0;
            for (int w = 0; w < 64; w++) { pref[w] = run; run += __popcll(keep[w]); }
        }
        __syncthreads();

        for (int i = tid; i < MAX_NMS; i += NTHR) {
            u64 wv = keep[i >> 6];
            int b = i & 63;
            if ((wv >> b) & 1ULL) {
                unsigned int rank = pref[i >> 6] +
                    (unsigned int)__popcll(wv & ((1ULL << b) - 1ULL));
                if (rank < (unsigned)MAX_DET) {
                    float4 bb = g_bbox[i];
                    float* o = out + (size_t)rank * 6;
                    o[0] = bb.x; o[1] = bb.y; o[2] = bb.z; o[3] = bb.w;
                    o[4] = g_score[i]; o[5] = g_clsf[i];
                }
            }
        }
    }
}

// ---------------- launch: ONE node ----------------
extern "C" void kernel_launch(void* const* d_in, const int* in_sizes, int n_in,
                              void* d_out, int out_size) {
    const float* pred = (const float*)d_in[0];
    float* out = (float*)d_out;
    yolo_all<<<NBLK, NTHR>>>(pred, out);
}

// round 10
// speedup vs baseline: 1.0624x; 1.0624x over previous
#include <cuda_runtime.h>
#include <stdint.h>

#define N        100800
#define NC       80
#define STRIDE   85
#define MAX_NMS  4096
#define MAX_DET  1000
#define CAP      16384
#define NB       256
#define KBASE    0x3ECCu
#define CONF_T   0.4f
#define IOU_T    0.45f
#define MAX_WH   7680.0f
#define ECAP     4096
#define NBLK     148
#define NTHR     1024
#define NTILE    2080           // 64*65/2 upper-tri 64x64 tiles

typedef unsigned long long u64;

// ---------------- scratch ----------------
__device__ unsigned int g_hist[NB];
__device__ unsigned int g_boff[NB];
__device__ unsigned int g_bcnt[NB];
__device__ unsigned int g_key[N];
__device__ unsigned int g_cutoff, g_total, g_bmax, g_ecnt;
__device__ u64          g_cand[CAP];
__device__ float4       g_obox[MAX_NMS];
__device__ float        g_area[MAX_NMS];
__device__ float4       g_bbox[MAX_NMS];
__device__ float        g_score[MAX_NMS];
__device__ float        g_clsf[MAX_NMS];
__device__ unsigned int g_edge[ECAP];

// ---------------- software grid barrier ----------------
__device__ unsigned int          bar_cnt = 0;
__device__ volatile unsigned int bar_gen = 0;

__device__ __forceinline__ void gsync() {
    __syncthreads();
    if (threadIdx.x == 0) {
        unsigned int gen = bar_gen;
        __threadfence();
        if (atomicAdd(&bar_cnt, 1u) == NBLK - 1u) {
            atomicExch(&bar_cnt, 0u);
            __threadfence();
            bar_gen = gen + 1u;
        } else {
            while (bar_gen == gen) {}
            __threadfence();
        }
    }
    __syncthreads();
}

// ---------------- decode one rank ----------------
__device__ __forceinline__ void decode_rank(const float* __restrict__ pred,
                                            u64 key, int r) {
    unsigned int kb  = (unsigned int)(key >> 32);
    unsigned int idx = ~(unsigned int)(key & 0xFFFFFFFFu);
    const float* row = pred + (size_t)idx * STRIDE;
    float x = row[0], y = row[1], w = row[2], h = row[3], obj = row[4];
    float bestv = -1.0f; int bestc = 0;
#pragma unroll 8
    for (int c = 0; c < NC; c++) {
        float p = __fmul_rn(row[5 + c], obj);
        if (p > bestv) { bestv = p; bestc = c; }
    }
    float hw = __fmul_rn(w, 0.5f), hh = __fmul_rn(h, 0.5f);
    float x1 = __fsub_rn(x, hw), y1 = __fsub_rn(y, hh);
    float x2 = __fadd_rn(x, hw), y2 = __fadd_rn(y, hh);
    float cf = (float)bestc;
    float off = __fmul_rn(cf, MAX_WH);
    float ox1 = __fadd_rn(x1, off), oy1 = __fadd_rn(y1, off);
    float ox2 = __fadd_rn(x2, off), oy2 = __fadd_rn(y2, off);
    float area = __fmul_rn(__fsub_rn(ox2, ox1), __fsub_rn(oy2, oy1));
    g_obox[r]  = make_float4(ox1, oy1, ox2, oy2);
    g_area[r]  = area;
    g_bbox[r]  = make_float4(x1, y1, x2, y2);
    g_score[r] = __uint_as_float(kb);
    g_clsf[r]  = cf;
}

// ---------------- fused pipeline ----------------
__global__ void __launch_bounds__(NTHR, 1)
yolo_all(const float* __restrict__ pred, float* __restrict__ out) {
    __shared__ u64          sbuf[4096];     // 32KB: bucket (u64) / edges (2x4096 u32)
    __shared__ unsigned int shist[NB];
    __shared__ float4       cob[64];
    __shared__ float        car[64];
    __shared__ u64          keep[64];
    __shared__ unsigned int pref[64];
    __shared__ int          s_bmax;

    const int tid = threadIdx.x;
    const int bid = blockIdx.x;

    // ---------- P1: zero counters + output ----------
    if (bid == 0) {
        if (tid < NB) g_hist[tid] = 0u;
        if (tid == 0) g_ecnt = 0u;
    }
    if (bid == 1) {
        for (int j = tid; j < MAX_DET * 6; j += NTHR) out[j] = 0.0f;
    }
    gsync();

    // ---------- P2: warp-per-anchor score (obj-skip + REDUX) ----------
    if (tid < NB) shist[tid] = 0u;
    __syncthreads();
    {
        int lane = tid & 31;
        int gw   = bid * (NTHR / 32) + (tid >> 5);
        const int nwarps = NBLK * (NTHR / 32);
        for (int a = gw; a < N; a += nwarps) {
            const float* r = pred + (size_t)a * STRIDE;
            float v0 = r[lane];                          // covers obj + cls[0..26]
            float obj = __shfl_sync(0xffffffffu, v0, 4);
            unsigned int key = 0u;
            if (obj > CONF_T) {                          // else conf<=obj<=0.4
                float v1 = r[lane + 32];
                float v2 = (lane < 21) ? r[lane + 64] : 0.0f;
                float m = 0.0f;
                if (lane >= 5) m = __fmul_rn(v0, obj);
                m = fmaxf(m, __fmul_rn(v1, obj));
                if (lane < 21) m = fmaxf(m, __fmul_rn(v2, obj));
                // m >= 0 for all lanes -> float bits monotone
                unsigned int mu = __reduce_max_sync(0xffffffffu, __float_as_uint(m));
                float mm = __uint_as_float(mu);
                if (mm > CONF_T) key = mu;
            }
            if (lane == 0) {
                g_key[a] = key;
                if (key) {
                    unsigned int b = (key >> 16) - KBASE;
                    if (b > 255u) b = 255u;
                    atomicAdd(&shist[b], 1u);
                }
            }
        }
    }
    __syncthreads();
    if (tid < NB && shist[tid]) atomicAdd(&g_hist[tid], shist[tid]);
    gsync();

    // ---------- P3: suffix scan (block 0) ----------
    if (bid == 0) {
        if (tid == 0) s_bmax = 0;
        unsigned int h = 0u;
        if (tid < NB) { h = g_hist[tid]; shist[tid] = h; }
        __syncthreads();
        for (int off = 1; off < NB; off <<= 1) {
            unsigned int v = 0u;
            if (tid < NB && tid + off < NB) v = shist[tid + off];
            __syncthreads();
            if (tid < NB) shist[tid] += v;
            __syncthreads();
        }
        if (tid < NB) {
            g_boff[tid] = (tid < NB - 1) ? shist[tid + 1] : 0u;
            g_bcnt[tid] = 0u;
            unsigned int st = shist[tid];
            if (st >= (unsigned)MAX_NMS &&
                (tid == NB - 1 || shist[tid + 1] < (unsigned)MAX_NMS)) {
                g_cutoff = (unsigned)tid;
                g_total  = st;
            }
            if (h) atomicMax(&s_bmax, tid);
        }
        __syncthreads();
        if (tid == 0) {
            g_bmax = (unsigned)s_bmax;
            if (shist[0] < (unsigned)MAX_NMS) { g_cutoff = 0u; g_total = shist[0]; }
        }
    }
    gsync();

    // ---------- P4: gather into bucket segments ----------
    {
        unsigned int cutoff = g_cutoff;
        for (int i = bid * NTHR + tid; i < N; i += NBLK * NTHR) {
            unsigned int key = g_key[i];
            if (!key) continue;
            unsigned int b = (key >> 16) - KBASE;
            if (b > 255u) b = 255u;
            if (b < cutoff) continue;
            unsigned int pos = g_boff[b] + atomicAdd(&g_bcnt[b], 1u);
            if (pos < CAP)
                g_cand[pos] = ((u64)key << 32) | (unsigned int)(~(unsigned int)i);
        }
    }
    gsync();

    // ---------- P5: per-bucket rank-by-count + fused decode ----------
    {
        unsigned int cutoff = g_cutoff, bmax = g_bmax;
        unsigned int limit = g_total;
        if (limit > (unsigned)MAX_NMS) limit = MAX_NMS;
        for (unsigned int b = cutoff + bid; b <= bmax; b += NBLK) {
            unsigned int L = g_hist[b];
            if (L == 0) continue;
            unsigned int off = g_boff[b];
            if (off >= limit) continue;
            if (L > 4096u) L = 4096u;
            if (L == 1) {
                if (tid == 0) decode_rank(pred, g_cand[off], off);
                continue;
            }
            for (unsigned int j = tid; j < L; j += NTHR) sbuf[j] = g_cand[off + j];
            __syncthreads();
            if (L <= 1024u) {
                // rank-by-count: keys distinct, descending rank = #greater
                if (tid < (int)L) {
                    u64 mine = sbuf[tid];
                    unsigned int cnt = 0;
                    for (unsigned int j = 0; j < L; j++)
                        cnt += (sbuf[j] > mine);
                    unsigned int r = off + cnt;
                    if (r < limit) decode_rank(pred, mine, (int)r);
                }
            } else {
                // bitonic fallback (rare)
                unsigned int P = 2; while (P < L) P <<= 1;
                for (unsigned int j = L + tid; j < P; j += NTHR) sbuf[j] = 0ULL;
                __syncthreads();
                for (unsigned int k = 2; k <= P; k <<= 1) {
                    for (unsigned int j = k >> 1; j > 0; j >>= 1) {
                        for (unsigned int p = tid; p < P / 2; p += NTHR) {
                            unsigned int i = ((p & ~(j - 1)) << 1) | (p & (j - 1));
                            u64 a = sbuf[i], c = sbuf[i + j];
                            bool sw = ((i & k) == 0) ? (a < c) : (a > c);
                            if (sw) { sbuf[i] = c; sbuf[i + j] = a; }
                        }
                        __syncthreads();
                    }
                }
                for (unsigned int j = tid; j < L; j += NTHR) {
                    unsigned int r = off + j;
                    if (r < limit) decode_rank(pred, sbuf[j], (int)r);
                }
            }
            __syncthreads();
        }
    }
    gsync();

    // ---------- P6: sparse suppression edges ----------
    for (int e = bid; e < NTILE; e += NBLK) {
        int rb = 0, rem = e;
        while (rem >= 64 - rb) { rem -= 64 - rb; rb++; }
        int cb = rb + rem;
        {   // cooperative tile load: 256 threads for boxes, 64 for areas
            float* cobf = (float*)cob;
            const float* src = (const float*)(g_obox + cb * 64);
            if (tid < 256) cobf[tid] = src[tid];
            else if (tid < 320) car[tid - 256] = g_area[cb * 64 + (tid - 256)];
        }
        __syncthreads();
        int r   = tid >> 4;
        int row = rb * 64 + r;
        float4 a = g_obox[row];
        float  aa = g_area[row];
#pragma unroll
        for (int q = 0; q < 4; q++) {
            int k   = (tid & 15) + q * 16;
            int col = cb * 64 + k;
            if (col > row) {
                float4 bbx = cob[k];
                float ltx = fmaxf(a.x, bbx.x), lty = fmaxf(a.y, bbx.y);
                float rbx = fminf(a.z, bbx.z), rby = fminf(a.w, bbx.w);
                float w = fmaxf(__fsub_rn(rbx, ltx), 0.0f);
                float h = fmaxf(__fsub_rn(rby, lty), 0.0f);
                float inter = __fmul_rn(w, h);
                if (inter > 0.0f) {
                    float denom = __fadd_rn(__fsub_rn(__fadd_rn(aa, car[k]), inter), 1e-9f);
                    float iou = __fdiv_rn(inter, denom);
                    if (iou > IOU_T) {
                        unsigned int p = atomicAdd(&g_ecnt, 1u);
                        if (p < ECAP)
                            g_edge[p] = ((unsigned int)row << 12) | (unsigned int)col;
                    }
                }
            }
        }
        __syncthreads();
    }
    gsync();

    // ---------- P7: block 0 — rank-sort edges, greedy, emit ----------
    if (bid != 0) return;
    {
        unsigned int* se  = (unsigned int*)sbuf;        // [0..4096)
        unsigned int* se2 = ((unsigned int*)sbuf) + 4096;
        unsigned int E = g_ecnt;
        if (E > ECAP) E = ECAP;
        unsigned int total = g_total;
        if (total > (unsigned)MAX_NMS) total = MAX_NMS;

        if (tid < 64) {
            unsigned int base = tid * 64u;
            u64 w;
            if (total >= base + 64u) w = ~0ULL;
            else if (total <= base)  w = 0ULL;
            else w = (1ULL << (total - base)) - 1ULL;
            keep[tid] = w;
        }
        for (unsigned int i = tid; i < E; i += NTHR) se[i] = g_edge[i];
        __syncthreads();
        // rank-by-count ascending (edges distinct)
        for (unsigned int i = tid; i < E; i += NTHR) {
            unsigned int mine = se[i];
            unsigned int cnt = 0;
            for (unsigned int j = 0; j < E; j++) cnt += (se[j] < mine);
            se2[cnt] = mine;
        }
        __syncthreads();

        // sequential greedy over ascending-src edges == fori_loop semantics
        if (tid == 0) {
            for (unsigned int e = 0; e < E; e++) {
                unsigned int kk = se2[e];
                unsigned int s = kk >> 12, d = kk & 4095u;
                if ((keep[s >> 6] >> (s & 63u)) & 1ULL)
                    keep[d >> 6] &= ~(1ULL << (d & 63u));
            }
            unsigned int run = 0;
            for (int w = 0; w < 64; w++) { pref[w] = run; run += __popcll(keep[w]); }
        }
        __syncthreads();

        for (int i = tid; i < MAX_NMS; i += NTHR) {
            u64 wv = keep[i >> 6];
            int b = i & 63;
            if ((wv >> b) & 1ULL) {
                unsigned int rank = pref[i >> 6] +
                    (unsigned int)__popcll(wv & ((1ULL << b) - 1ULL));
                if (rank < (unsigned)MAX_DET) {
                    float4 bb = g_bbox[i];
                    float* o = out + (size_t)rank * 6;
                    o[0] = bb.x; o[1] = bb.y; o[2] = bb.z; o[3] = bb.w;
                    o[4] = g_score[i]; o[5] = g_clsf[i];
                }
            }
        }
    }
}

extern "C" void kernel_launch(void* const* d_in, const int* in_sizes, int n_in,
                              void* d_out, int out_size) {
    const float* pred = (const float*)d_in[0];
    float* out = (float*)d_out;
    yolo_all<<<NBLK, NTHR>>>(pred, out);
}